// round 4
// baseline (speedup 1.0000x reference)
#include <cuda_runtime.h>
#include <math.h>

#define IGNORE_LABEL (-100LL)
#define MAXROWS 16384

// per-row scratch — every slot is written unconditionally by row_kernel,
// so no zero-init pass is needed.
__device__ double g_pt[MAXROWS];     // per-token CE (0 if ignored)
__device__ int    g_flag[MAXROWS];   // bit0 = valid, bit1 = argmax==label

__device__ __forceinline__ float frcp_fast(float t) {
    float r;
    asm("rcp.approx.ftz.f32 %0, %1;" : "=f"(r) : "f"(t));
    return r;
}

__device__ __forceinline__ float smap(float v) {
    // s(x) = x<0 ? 1/(1-x) : x+1
    float r = frcp_fast(1.0f - v);
    return v < 0.0f ? r : v + 1.0f;
}

// one block per token row
__global__ void __launch_bounds__(256) row_kernel(
        const float* __restrict__ logits,
        const void* __restrict__ labels_raw,
        int V) {
    const int row = blockIdx.x;
    const int tid = threadIdx.x;
    const int nt  = blockDim.x;
    const float* __restrict__ x = logits + (size_t)row * V;

    // ---- labels dtype probe (warp 0; identical result in every block) ----
    // Interpret the first 32 entries as int64: 32*8B = 256B, in-bounds under
    // either dtype (labels buffer is >= rows*4 bytes, rows >= 64).
    __shared__ int s_is64;
    if (tid < 32) {
        long long v = ((const long long*)labels_raw)[tid];
        bool okv = (v >= 0 && v < (long long)V) || v == IGNORE_LABEL;
        unsigned m = __ballot_sync(0xffffffffu, okv);
        if (tid == 0) s_is64 = (m == 0xffffffffu);
    }

    float sumA = 0.f, sumB = 0.f;
    float lmax = -INFINITY;
    int   lidx = 0x7fffffff;

    const int V4 = V >> 2;
    const float4* __restrict__ x4 = (const float4*)x;
    #pragma unroll 8
    for (int i = tid; i < V4; i += nt) {
        float4 v = __ldg(&x4[i]);
        int base = i << 2;
        float s0 = smap(v.x);
        float s1 = smap(v.y);
        float s2 = smap(v.z);
        float s3 = smap(v.w);
        sumA += s0 + s1;
        sumB += s2 + s3;
        // strict > keeps first (smallest) index within a thread,
        // since per-thread visit order is strictly increasing index.
        if (v.x > lmax) { lmax = v.x; lidx = base + 0; }
        if (v.y > lmax) { lmax = v.y; lidx = base + 1; }
        if (v.z > lmax) { lmax = v.z; lidx = base + 2; }
        if (v.w > lmax) { lmax = v.w; lidx = base + 3; }
    }
    // tail (V not multiple of 4)
    for (int i = (V4 << 2) + tid; i < V; i += nt) {
        float v = __ldg(&x[i]);
        sumA += smap(v);
        if (v > lmax) { lmax = v; lidx = i; }
    }

    __shared__ float  ssum[256];
    __shared__ float  smax[256];
    __shared__ int    sidx[256];
    ssum[tid] = sumA + sumB;
    smax[tid] = lmax;
    sidx[tid] = lidx;
    __syncthreads();
    for (int s = nt >> 1; s > 0; s >>= 1) {
        if (tid < s) {
            ssum[tid] += ssum[tid + s];
            float mv = smax[tid + s]; int mi = sidx[tid + s];
            if (mv > smax[tid] || (mv == smax[tid] && mi < sidx[tid])) {
                smax[tid] = mv; sidx[tid] = mi;
            }
        }
        __syncthreads();
    }

    if (tid == 0) {
        long long label;
        if (s_is64) label = ((const long long*)labels_raw)[row];
        else        label = (long long)((const int*)labels_raw)[row];

        double pt = 0.0;
        int flag = 0;
        if (label >= 0 && label < (long long)V) {
            double xl = (double)x[(int)label];
            double sl = xl < 0.0 ? 1.0 / (1.0 - xl + 1e-30) : xl + 1.0;
            pt = log((double)ssum[0]) - log(sl);   // -log(s_label / sum)
            flag = 1 | (((long long)sidx[0] == label) ? 2 : 0);
        }
        g_pt[row]   = pt;
        g_flag[row] = flag;
    }
}

__global__ void __launch_bounds__(256) final_kernel(
        const float* __restrict__ qh,
        const float* __restrict__ qc,
        float* __restrict__ out, int Bn, int Lseq) {
    const int tid = threadIdx.x;
    __shared__ double rsum[256];
    __shared__ int    rval[256];
    __shared__ int    rcor[256];
    __shared__ float  s_Ltask, s_lh, s_lc;

    if (tid == 0) { s_Ltask = 0.f; s_lh = 0.f; s_lc = 0.f; }

    for (int b = 0; b < Bn; b++) {
        double ps = 0.0; int pv = 0, pc = 0;
        const int base = b * Lseq;
        for (int r = tid; r < Lseq; r += blockDim.x) {
            ps += g_pt[base + r];
            int f = g_flag[base + r];
            pv += f & 1;
            pc += (f >> 1) & 1;
        }
        rsum[tid] = ps; rval[tid] = pv; rcor[tid] = pc;
        __syncthreads();
        for (int s = blockDim.x >> 1; s > 0; s >>= 1) {
            if (tid < s) {
                rsum[tid] += rsum[tid + s];
                rval[tid] += rval[tid + s];
                rcor[tid] += rcor[tid + s];
            }
            __syncthreads();
        }
        if (tid == 0) {
            float cnt = (float)(rval[0] > 1 ? rval[0] : 1);
            s_Ltask += (float)rsum[0] / cnt;
            float t = (rcor[0] == rval[0]) ? 1.f : 0.f;
            float xh = qh[b];
            s_lh += fmaxf(xh, 0.f) - xh * t + log1pf(expf(-fabsf(xh)));
            float tc = 1.f / (1.f + expf(-xh));
            float xc = qc[b];
            s_lc += fmaxf(xc, 0.f) - xc * tc + log1pf(expf(-fabsf(xc)));
        }
        __syncthreads();
    }

    if (tid == 0) {
        float Ltask = s_Ltask / (float)Bn;
        float Lhalt = 0.5f * (s_lh / (float)Bn + s_lc / (float)Bn);
        out[0] = Ltask + Lhalt;
    }
}

extern "C" void kernel_launch(void* const* d_in, const int* in_sizes, int n_in,
                              void* d_out, int out_size) {
    // Identify inputs by size, not position.
    int li = 0;
    for (int i = 1; i < n_in; i++) if (in_sizes[i] > in_sizes[li]) li = i;
    int lab = -1;
    for (int i = 0; i < n_in; i++) {
        if (i == li) continue;
        if (lab < 0 || in_sizes[i] > in_sizes[lab]) lab = i;
    }
    int qi[2]; int nq = 0;
    for (int i = 0; i < n_in && nq < 2; i++) {
        if (i != li && i != lab) qi[nq++] = i;
    }

    const float* logits = (const float*)d_in[li];
    const void*  labels = d_in[lab];
    const float* qh     = (const float*)d_in[qi[0]];
    const float* qc     = (const float*)d_in[qi[1]];

    const int Bn   = in_sizes[qi[0]];
    const int rows = in_sizes[lab];
    const int Lseq = rows / Bn;
    const int V    = (int)((long long)in_sizes[li] / rows);

    row_kernel<<<rows, 256>>>(logits, labels, V);
    final_kernel<<<1, 256>>>(qh, qc, (float*)d_out, Bn, Lseq);
}